// round 7
// baseline (speedup 1.0000x reference)
#include <cuda_runtime.h>

// Problem dims
#define B  64
#define L  1024
#define D  64
#define H  512
#define LN_EPS 1e-5f

// Partitioning: 8 batch-groups x 16 j-slices = 128 CTAs
#define GB 8     // batch groups
#define GJ 16    // hidden-column slices
#define BC 8     // batches per CTA   (B / GB)
#define JC 32    // j columns per CTA (H / GJ)
#define KG 8     // k-groups (warps; each owns 64 k-columns)
#define NT 256   // threads per CTA = JC * KG

// SMEM: Whh [3][128 k4][JC] float4  +  h_s [BC][H] float  +  red [4][BC][4][JC] float
#define WHH_F4     (3 * 128 * JC)                 // 12288 float4 = 196608 B
#define RED_F      (4 * BC * 4 * JC)              // 4096 floats  = 16384 B
#define SMEM_BYTES (WHH_F4 * 16 + BC * H * 4 + RED_F * 4)   // 229376 B

typedef unsigned long long ull;

// Global scratch (static — no allocations allowed)
__device__ float g_h[2][B * H];                    // ping-pong hidden state
__device__ __align__(8) int g_flag[GB][GJ];        // per-producer step counters
__device__ int g_done[GB];                         // exit counters (for reset)

// ---------------- packed f32x2 helpers ----------------
__device__ __forceinline__ void ffma2(ull& acc, ull a, ull b) {
    asm("fma.rn.f32x2 %0, %1, %2, %0;" : "+l"(acc) : "l"(a), "l"(b));
}
__device__ __forceinline__ float upk_sum(ull v) {
    float lo, hi;
    asm("mov.b64 {%0, %1}, %2;" : "=f"(lo), "=f"(hi) : "l"(v));
    return lo + hi;
}

// wait until both adjacent flags reach target (64-bit acquire poll)
__device__ __forceinline__ void wait_pair(const int* f, int target) {
    ull v;
    unsigned lo, hi;
    do {
        asm volatile("ld.acquire.gpu.global.b64 %0, [%1];"
                     : "=l"(v) : "l"(f) : "memory");
        lo = (unsigned)v;
        hi = (unsigned)(v >> 32);
    } while (lo < (unsigned)target || hi < (unsigned)target);
}

// ---------------- persistent recurrent kernel ----------------
__global__ void __launch_bounds__(NT, 1)
gru_kernel(const float* __restrict__ x,     // (B, L, D)
           const float* __restrict__ h0,    // (1, B, H)
           const float* __restrict__ W_ih,  // (3H, D)
           const float* __restrict__ W_hh,  // (3H, H)
           const float* __restrict__ b_ih,  // (3H)
           const float* __restrict__ b_hh,  // (3H)
           float* __restrict__ out_hseq,    // (B, L, H) — raw h, LN'd later in place
           float* __restrict__ out_hN)      // (1, B, H)
{
    extern __shared__ float4 smem[];
    float4* Whh_s = smem;                              // [3][128][JC] float4
    float*  h_s   = (float*)(smem + WHH_F4);           // [BC][H]
    float*  red   = h_s + BC * H;                      // [4 gates][BC][4][JC]

    const int tid = threadIdx.x;
    const int j   = tid & 31;        // lane = hidden column within slice
    const int kg  = tid >> 5;        // warp id = k-group (0..7), 64 k each
    const int grp = blockIdx.x / GJ; // batch group
    const int slc = blockIdx.x % GJ; // j slice
    const int jg  = slc * JC + j;    // global hidden column
    const int bg0 = grp * BC;        // first global batch

    // ---- load W_hh slice into SMEM (once) ----
    for (int rbase = 0; rbase < 96; rbase += 8) {
        int r  = rbase + kg;
        int g  = r >> 5;
        int jr = r & 31;
        const float4* src = (const float4*)(W_hh + ((size_t)(g * H + slc * JC + jr)) * H);
        #pragma unroll
        for (int c = 0; c < 4; c++) {
            int k4 = j + c * 32;
            Whh_s[(g * 128 + k4) * JC + jr] = src[k4];
        }
    }

    // ---- W_ih slice into registers (packed f32x2): 8 floats of D per kg ----
    ull wih[3][4];
    #pragma unroll
    for (int g = 0; g < 3; g++) {
        const ull* src = (const ull*)(W_ih + (size_t)(g * H + jg) * D) + kg * 4;
        #pragma unroll
        for (int i = 0; i < 4; i++) wih[g][i] = src[i];
    }

    // ---- biases for finalize (this thread's j column) ----
    const float bsr  = b_ih[jg]         + b_hh[jg];
    const float bsz  = b_ih[H + jg]     + b_hh[H + jg];
    const float bin_ = b_ih[2 * H + jg];
    const float bhn  = b_hh[2 * H + jg];

    // ---- stage initial h ----
    {
        const float4* src = (const float4*)(h0 + (size_t)bg0 * H);
        float4* dst = (float4*)h_s;
        #pragma unroll
        for (int i = 0; i < 4; i++) dst[tid + i * NT] = src[tid + i * NT];
    }

    // ---- input projection for t=0 ----
    ull giR[BC], giZ[BC], giN[BC];
    #define COMPUTE_GI(tt) do {                                                  \
        _Pragma("unroll")                                                        \
        for (int b = 0; b < BC; b++) {                                           \
            const ull* xp = (const ull*)(x + ((size_t)(bg0 + b) * L + (tt)) * D) \
                            + kg * 4;                                            \
            ull x0 = xp[0], x1 = xp[1], x2 = xp[2], x3 = xp[3];                  \
            giR[b] = 0; giZ[b] = 0; giN[b] = 0;                                  \
            ffma2(giR[b], wih[0][0], x0); ffma2(giR[b], wih[0][1], x1);          \
            ffma2(giR[b], wih[0][2], x2); ffma2(giR[b], wih[0][3], x3);          \
            ffma2(giZ[b], wih[1][0], x0); ffma2(giZ[b], wih[1][1], x1);          \
            ffma2(giZ[b], wih[1][2], x2); ffma2(giZ[b], wih[1][3], x3);          \
            ffma2(giN[b], wih[2][0], x0); ffma2(giN[b], wih[2][1], x1);          \
            ffma2(giN[b], wih[2][2], x2); ffma2(giN[b], wih[2][3], x3);          \
        }                                                                        \
    } while (0)
    COMPUTE_GI(0);

    __syncthreads();

    for (int t = 0; t < L; t++) {
        // ---- per-warp restage: wait only on this warp's 2 producers ----
        if (t > 0) {
            wait_pair(&g_flag[grp][2 * kg], t);
            const float* src = g_h[(t - 1) & 1] + (size_t)bg0 * H + 64 * kg;
            #pragma unroll
            for (int i = 0; i < 4; i++) {
                int idx = j + 32 * i;            // 0..127
                int b = idx >> 4, p = idx & 15;
                float4 val = *(const float4*)(src + (size_t)b * H + p * 4);
                *(float4*)(h_s + b * H + 64 * kg + p * 4) = val;
            }
            __syncwarp();
        }

        // ---- recurrent GEMM: seed accumulators with gi ----
        ull ar[BC], az[BC], an_[BC], ahn[BC];
        #pragma unroll
        for (int b = 0; b < BC; b++) {
            ar[b] = giR[b]; az[b] = giZ[b]; an_[b] = giN[b]; ahn[b] = 0;
        }

        const int kb = kg * 16;
        #pragma unroll 4
        for (int k4m = 0; k4m < 16; k4m++) {
            const int k4 = kb + k4m;
            const ulonglong2 wr = *(const ulonglong2*)&Whh_s[(0 * 128 + k4) * JC + j];
            const ulonglong2 wz = *(const ulonglong2*)&Whh_s[(1 * 128 + k4) * JC + j];
            const ulonglong2 wn = *(const ulonglong2*)&Whh_s[(2 * 128 + k4) * JC + j];
            #pragma unroll
            for (int b = 0; b < BC; b++) {
                const ulonglong2 hv = *(const ulonglong2*)&h_s[b * H + k4 * 4];
                ffma2(ar[b],  wr.x, hv.x);  ffma2(ar[b],  wr.y, hv.y);
                ffma2(az[b],  wz.x, hv.x);  ffma2(az[b],  wz.y, hv.y);
                ffma2(ahn[b], wn.x, hv.x);  ffma2(ahn[b], wn.y, hv.y);
            }
        }

        // ---- two-phase cross-kg reduction in SMEM ----
        const int kgm = kg & 3;
        if (kg >= 4) {
            #pragma unroll
            for (int b = 0; b < BC; b++) {
                red[((0 * BC + b) * 4 + kgm) * JC + j] = upk_sum(ar[b]);
                red[((1 * BC + b) * 4 + kgm) * JC + j] = upk_sum(az[b]);
                red[((2 * BC + b) * 4 + kgm) * JC + j] = upk_sum(ahn[b]);
                red[((3 * BC + b) * 4 + kgm) * JC + j] = upk_sum(an_[b]);
            }
        }
        __syncthreads();
        if (kg < 4) {
            #pragma unroll
            for (int b = 0; b < BC; b++) {
                red[((0 * BC + b) * 4 + kgm) * JC + j] += upk_sum(ar[b]);
                red[((1 * BC + b) * 4 + kgm) * JC + j] += upk_sum(az[b]);
                red[((2 * BC + b) * 4 + kgm) * JC + j] += upk_sum(ahn[b]);
                red[((3 * BC + b) * 4 + kgm) * JC + j] += upk_sum(an_[b]);
            }
        }
        __syncthreads();

        // ---- finalize: one (b=kg, j=lane) pair per thread ----
        {
            const int b = kg;
            float sr = 0.f, sz = 0.f, shn = 0.f, sn = 0.f;
            #pragma unroll
            for (int c = 0; c < 4; c++) {
                sr  += red[((0 * BC + b) * 4 + c) * JC + j];
                sz  += red[((1 * BC + b) * 4 + c) * JC + j];
                shn += red[((2 * BC + b) * 4 + c) * JC + j];
                sn  += red[((3 * BC + b) * 4 + c) * JC + j];
            }
            float r = 1.f / (1.f + __expf(-(sr + bsr)));
            float z = 1.f / (1.f + __expf(-(sz + bsz)));
            float n = tanhf(sn + bin_ + r * (shn + bhn));
            float hold = h_s[b * H + jg];
            float hnew = fmaf(z, hold - n, n);   // (1-z)n + z*h

            const int bglob = bg0 + b;
            g_h[t & 1][(size_t)bglob * H + jg] = hnew;
            out_hseq[((size_t)bglob * L + t) * H + jg] = hnew;
            if (t == L - 1) out_hN[(size_t)bglob * H + jg] = hnew;
        }

        __syncthreads();   // STGs done; red/h_s reads complete before reuse

        if (t + 1 < L) {
            if (tid == 0) {
                asm volatile("red.release.gpu.global.add.u32 [%0], 1;"
                             :: "l"(&g_flag[grp][slc]) : "memory");
            }
            COMPUTE_GI(t + 1);   // hidden behind producers' tails
        }
    }

    // ---- exit protocol: reset flags for next graph replay ----
    if (tid == 0) {
        asm volatile("red.release.gpu.global.add.u32 [%0], 1;"
                     :: "l"(&g_done[grp]) : "memory");
        if (slc == 0) {
            int c;
            do {
                asm volatile("ld.acquire.gpu.global.b32 %0, [%1];"
                             : "=r"(c) : "l"(&g_done[grp]) : "memory");
            } while (c < GJ);
            #pragma unroll
            for (int p = 0; p < GJ; p++) g_flag[grp][p] = 0;
            g_done[grp] = 0;
        }
    }
}

// ---------------- LayerNorm (in place) + prediction GEMM, 4 rows/block ----------------
#define RPB 4
__global__ void __launch_bounds__(128)
ln_pred_kernel(const float* __restrict__ gamma, const float* __restrict__ beta,
               const float* __restrict__ Wp,    const float* __restrict__ bp,
               float* __restrict__ hseq,        float* __restrict__ xhat)
{
    __shared__ float sh[RPB][H];    // 8 KB

    const int row0 = blockIdx.x * RPB;
    const int tid  = threadIdx.x;
    const int w    = tid >> 5;      // warp = row for LN, jo-group for GEMM
    const int l    = tid & 31;

    // ---- LN: warp w normalizes row row0+w ----
    float* hp = hseq + (size_t)(row0 + w) * H;
    float4 v[4];
    float s = 0.f, q = 0.f;
    #pragma unroll
    for (int i = 0; i < 4; i++) {
        v[i] = ((const float4*)hp)[l + 32 * i];
        s += v[i].x + v[i].y + v[i].z + v[i].w;
        q += v[i].x * v[i].x + v[i].y * v[i].y + v[i].z * v[i].z + v[i].w * v[i].w;
    }
    #pragma unroll
    for (int o = 16; o; o >>= 1) {
        s += __shfl_xor_sync(0xffffffffu, s, o);
        q += __shfl_xor_sync(0xffffffffu, q, o);
    }
    const float mu = s * (1.f / H);
    const float rs = rsqrtf(q * (1.f / H) - mu * mu + LN_EPS);

    #pragma unroll
    for (int i = 0; i < 4; i++) {
        float4 g4 = ((const float4*)gamma)[l + 32 * i];
        float4 b4 = ((const float4*)beta)[l + 32 * i];
        float4 o;
        o.x = (v[i].x - mu) * rs * g4.x + b4.x;
        o.y = (v[i].y - mu) * rs * g4.y + b4.y;
        o.z = (v[i].z - mu) * rs * g4.z + b4.z;
        o.w = (v[i].w - mu) * rs * g4.w + b4.w;
        ((float4*)hp)[l + 32 * i] = o;              // in-place normalized
        ((float4*)&sh[w][0])[l + 32 * i] = o;
    }
    __syncthreads();

    // ---- all 4 rows' k-chunk into registers (reused across 16 jo) ----
    float4 hreg[RPB][4];
    #pragma unroll
    for (int r = 0; r < RPB; r++)
        #pragma unroll
        for (int i = 0; i < 4; i++)
            hreg[r][i] = ((const float4*)&sh[r][0])[l + 32 * i];

    // ---- GEMM: warp w computes jo = 16w .. 16w+15 for all 4 rows ----
    #pragma unroll 4
    for (int jj = 0; jj < 16; jj++) {
        const int jo = w * 16 + jj;
        const float4* wp4 = (const float4*)(Wp + (size_t)jo * H);
        float acc[RPB] = {0.f, 0.f, 0.f, 0.f};
        #pragma unroll
        for (int i = 0; i < 4; i++) {
            float4 wv = wp4[l + 32 * i];
            #pragma unroll
            for (int r = 0; r < RPB; r++) {
                acc[r] += wv.x * hreg[r][i].x + wv.y * hreg[r][i].y
                        + wv.z * hreg[r][i].z + wv.w * hreg[r][i].w;
            }
        }
        #pragma unroll
        for (int o = 16; o; o >>= 1)
            #pragma unroll
            for (int r = 0; r < RPB; r++)
                acc[r] += __shfl_xor_sync(0xffffffffu, acc[r], o);
        if (l == 0) {
            const float bj = bp[jo];
            #pragma unroll
            for (int r = 0; r < RPB; r++)
                xhat[(size_t)(row0 + r) * D + jo] = acc[r] + bj;
        }
    }
}

extern "C" void kernel_launch(void* const* d_in, const int* in_sizes, int n_in,
                              void* d_out, int out_size)
{
    const float* x      = (const float*)d_in[0];
    const float* h0     = (const float*)d_in[1];
    const float* W_ih   = (const float*)d_in[2];
    const float* W_hh   = (const float*)d_in[3];
    const float* b_ih   = (const float*)d_in[4];
    const float* b_hh   = (const float*)d_in[5];
    const float* gamma  = (const float*)d_in[6];
    const float* beta   = (const float*)d_in[7];
    const float* W_pred = (const float*)d_in[8];
    const float* b_pred = (const float*)d_in[9];

    float* out      = (float*)d_out;
    float* out_hseq = out;                                   // (B, L, H)
    float* out_hN   = out + (size_t)B * L * H;               // (1, B, H)
    float* out_xhat = out_hN + (size_t)B * H;                // (B, L, D)

    cudaFuncSetAttribute(gru_kernel, cudaFuncAttributeMaxDynamicSharedMemorySize,
                         SMEM_BYTES);

    gru_kernel<<<GB * GJ, NT, SMEM_BYTES>>>(x, h0, W_ih, W_hh, b_ih, b_hh,
                                            out_hseq, out_hN);
    ln_pred_kernel<<<(B * L) / RPB, 128>>>(gamma, beta, W_pred, b_pred,
                                           out_hseq, out_xhat);
}

// round 9
// speedup vs baseline: 1.0874x; 1.0874x over previous
#include <cuda_runtime.h>

// Problem dims
#define B  64
#define L  1024
#define D  64
#define H  512
#define LN_EPS 1e-5f

// Partitioning: 8 batch-groups x 16 j-slices = 128 CTAs
#define GB 8     // batch groups
#define GJ 16    // hidden-column slices
#define BC 8     // batches per CTA   (B / GB)
#define JC 32    // j columns per CTA (H / GJ)
#define KG 8     // k-groups (warps; each owns 64 k-columns)
#define NT 256   // threads per CTA = JC * KG

// SMEM: Whh [3][128 k4][JC] float4  +  h_s [BC][H] float  +  red [4][BC][4][JC] float
#define WHH_F4     (3 * 128 * JC)                 // 12288 float4 = 196608 B
#define RED_F      (4 * BC * 4 * JC)              // 4096 floats  = 16384 B
#define SMEM_BYTES (WHH_F4 * 16 + BC * H * 4 + RED_F * 4)   // 229376 B

typedef unsigned long long ull;

// Global scratch (static — no allocations allowed)
__device__ float g_h[2][B * H];   // ping-pong hidden state
__device__ int   g_cnt[GB];       // per-group monotonic release counters (8/CTA/step)
__device__ int   g_done[GB];      // exit counters (for reset)

// ---------------- packed f32x2 helpers ----------------
__device__ __forceinline__ void ffma2(ull& acc, ull a, ull b) {
    asm("fma.rn.f32x2 %0, %1, %2, %0;" : "+l"(acc) : "l"(a), "l"(b));
}
__device__ __forceinline__ float upk_sum(ull v) {
    float lo, hi;
    asm("mov.b64 {%0, %1}, %2;" : "=f"(lo), "=f"(hi) : "l"(v));
    return lo + hi;
}

// ---------------- persistent recurrent kernel ----------------
__global__ void __launch_bounds__(NT, 1)
gru_kernel(const float* __restrict__ x,     // (B, L, D)
           const float* __restrict__ h0,    // (1, B, H)
           const float* __restrict__ W_ih,  // (3H, D)
           const float* __restrict__ W_hh,  // (3H, H)
           const float* __restrict__ b_ih,  // (3H)
           const float* __restrict__ b_hh,  // (3H)
           float* __restrict__ out_hseq,    // (B, L, H) — raw h, LN'd later in place
           float* __restrict__ out_hN)      // (1, B, H)
{
    extern __shared__ float4 smem[];
    float4* Whh_s = smem;                              // [3][128][JC] float4
    float*  h_s   = (float*)(smem + WHH_F4);           // [BC][H]
    float*  red   = h_s + BC * H;                      // [4 gates][BC][4][JC]

    const int tid = threadIdx.x;
    const int j   = tid & 31;        // lane = hidden column within slice
    const int kg  = tid >> 5;        // warp id = k-group (0..7), 64 k each
    const int grp = blockIdx.x / GJ; // batch group
    const int slc = blockIdx.x % GJ; // j slice
    const int jg  = slc * JC + j;    // global hidden column
    const int bg0 = grp * BC;        // first global batch

    // ---- load W_hh slice into SMEM (once) ----
    for (int rbase = 0; rbase < 96; rbase += 8) {
        int r  = rbase + kg;
        int g  = r >> 5;
        int jr = r & 31;
        const float4* src = (const float4*)(W_hh + ((size_t)(g * H + slc * JC + jr)) * H);
        #pragma unroll
        for (int c = 0; c < 4; c++) {
            int k4 = j + c * 32;
            Whh_s[(g * 128 + k4) * JC + jr] = src[k4];
        }
    }

    // ---- W_ih slice into registers (packed f32x2): 8 floats of D per kg ----
    ull wih[3][4];
    #pragma unroll
    for (int g = 0; g < 3; g++) {
        const ull* src = (const ull*)(W_ih + (size_t)(g * H + jg) * D) + kg * 4;
        #pragma unroll
        for (int i = 0; i < 4; i++) wih[g][i] = src[i];
    }

    // ---- biases for finalize (this thread's j column) ----
    const float bsr  = b_ih[jg]         + b_hh[jg];
    const float bsz  = b_ih[H + jg]     + b_hh[H + jg];
    const float bin_ = b_ih[2 * H + jg];
    const float bhn  = b_hh[2 * H + jg];

    // ---- stage initial h ----
    {
        const float4* src = (const float4*)(h0 + (size_t)bg0 * H);
        float4* dst = (float4*)h_s;
        #pragma unroll
        for (int i = 0; i < 4; i++) dst[tid + i * NT] = src[tid + i * NT];
    }

    // ---- input projection for t=0 ----
    ull giR[BC], giZ[BC], giN[BC];
    #define COMPUTE_GI(tt) do {                                                  \
        _Pragma("unroll")                                                        \
        for (int b = 0; b < BC; b++) {                                           \
            const ull* xp = (const ull*)(x + ((size_t)(bg0 + b) * L + (tt)) * D) \
                            + kg * 4;                                            \
            ull x0 = xp[0], x1 = xp[1], x2 = xp[2], x3 = xp[3];                  \
            giR[b] = 0; giZ[b] = 0; giN[b] = 0;                                  \
            ffma2(giR[b], wih[0][0], x0); ffma2(giR[b], wih[0][1], x1);          \
            ffma2(giR[b], wih[0][2], x2); ffma2(giR[b], wih[0][3], x3);          \
            ffma2(giZ[b], wih[1][0], x0); ffma2(giZ[b], wih[1][1], x1);          \
            ffma2(giZ[b], wih[1][2], x2); ffma2(giZ[b], wih[1][3], x3);          \
            ffma2(giN[b], wih[2][0], x0); ffma2(giN[b], wih[2][1], x1);          \
            ffma2(giN[b], wih[2][2], x2); ffma2(giN[b], wih[2][3], x3);          \
        }                                                                        \
    } while (0)
    COMPUTE_GI(0);

    __syncthreads();

    for (int t = 0; t < L; t++) {
        // ---- recurrent GEMM over this warp's k-slab, seeded with gi ----
        ull ar[BC], az[BC], an_[BC], ahn[BC];
        #pragma unroll
        for (int b = 0; b < BC; b++) {
            ar[b] = giR[b]; az[b] = giZ[b]; an_[b] = giN[b]; ahn[b] = 0;
        }

        const int kb = kg * 16;
        #pragma unroll 4
        for (int k4m = 0; k4m < 16; k4m++) {
            const int k4 = kb + k4m;
            const ulonglong2 wr = *(const ulonglong2*)&Whh_s[(0 * 128 + k4) * JC + j];
            const ulonglong2 wz = *(const ulonglong2*)&Whh_s[(1 * 128 + k4) * JC + j];
            const ulonglong2 wn = *(const ulonglong2*)&Whh_s[(2 * 128 + k4) * JC + j];
            #pragma unroll
            for (int b = 0; b < BC; b++) {
                const ulonglong2 hv = *(const ulonglong2*)&h_s[b * H + k4 * 4];
                ffma2(ar[b],  wr.x, hv.x);  ffma2(ar[b],  wr.y, hv.y);
                ffma2(az[b],  wz.x, hv.x);  ffma2(az[b],  wz.y, hv.y);
                ffma2(ahn[b], wn.x, hv.x);  ffma2(ahn[b], wn.y, hv.y);
            }
        }

        // ---- two-phase cross-kg reduction in SMEM ----
        const int kgm = kg & 3;
        if (kg >= 4) {
            #pragma unroll
            for (int b = 0; b < BC; b++) {
                red[((0 * BC + b) * 4 + kgm) * JC + j] = upk_sum(ar[b]);
                red[((1 * BC + b) * 4 + kgm) * JC + j] = upk_sum(az[b]);
                red[((2 * BC + b) * 4 + kgm) * JC + j] = upk_sum(ahn[b]);
                red[((3 * BC + b) * 4 + kgm) * JC + j] = upk_sum(an_[b]);
            }
        }
        __syncthreads();
        if (kg < 4) {
            #pragma unroll
            for (int b = 0; b < BC; b++) {
                red[((0 * BC + b) * 4 + kgm) * JC + j] += upk_sum(ar[b]);
                red[((1 * BC + b) * 4 + kgm) * JC + j] += upk_sum(az[b]);
                red[((2 * BC + b) * 4 + kgm) * JC + j] += upk_sum(ahn[b]);
                red[((3 * BC + b) * 4 + kgm) * JC + j] += upk_sum(an_[b]);
            }
        }
        __syncthreads();

        // ---- finalize: one (b=kg, j=lane) pair per thread; fast activations ----
        {
            const int b = kg;
            float sr = 0.f, sz = 0.f, shn = 0.f, sn = 0.f;
            #pragma unroll
            for (int c = 0; c < 4; c++) {
                sr  += red[((0 * BC + b) * 4 + c) * JC + j];
                sz  += red[((1 * BC + b) * 4 + c) * JC + j];
                shn += red[((2 * BC + b) * 4 + c) * JC + j];
                sn  += red[((3 * BC + b) * 4 + c) * JC + j];
            }
            float er = __expf(-(sr + bsr));
            float r  = __fdividef(1.f, 1.f + er);
            float ez = __expf(-(sz + bsz));
            float z  = __fdividef(1.f, 1.f + ez);
            float ta = sn + bin_ + r * (shn + bhn);
            ta = fminf(fmaxf(ta, -20.f), 20.f);          // keep exp finite
            float en = __expf(-2.f * ta);
            float n  = __fdividef(1.f - en, 1.f + en);   // tanh(ta)
            float hold = h_s[b * H + jg];
            float hnew = fmaf(z, hold - n, n);           // (1-z)n + z*h

            const int bglob = bg0 + b;
            g_h[t & 1][(size_t)bglob * H + jg] = hnew;
            out_hseq[((size_t)bglob * L + t) * H + jg] = hnew;
            if (t == L - 1) out_hN[(size_t)bglob * H + jg] = hnew;
        }

        if (t + 1 < L) {
            // per-warp release: this warp's g_h row is done
            __syncwarp();
            if (j == 0) {
                asm volatile("red.release.gpu.global.add.u32 [%0], 1;"
                             :: "l"(&g_cnt[grp]) : "memory");
            }
            // input projection for t+1 — overlapped with other CTAs' tails
            COMPUTE_GI(t + 1);

            if (tid == 0) {
                const int target = KG * GJ * (t + 1);    // 8 releases per CTA per step
                int c;
                do {
                    asm volatile("ld.acquire.gpu.global.b32 %0, [%1];"
                                 : "=r"(c) : "l"(&g_cnt[grp]) : "memory");
                } while (c < target);
            }
            __syncthreads();   // flag observed; red + h_s safe to overwrite

            // warp-local restage: only this warp's 64-column k-slab
            {
                const float* src = g_h[t & 1] + (size_t)bg0 * H + 64 * kg;
                float* dst = h_s + 64 * kg;
                #pragma unroll
                for (int i = 0; i < 4; i++) {
                    int idx = i * 32 + j;          // 0..127 float4s in slab
                    int b = idx >> 4, c4 = idx & 15;
                    float4 val = *(const float4*)(src + (size_t)b * H + c4 * 4);
                    *(float4*)(dst + b * H + c4 * 4) = val;
                }
                __syncwarp();
            }
        }
    }

    // ---- exit protocol: reset counters for next graph replay ----
    if (tid == 0) {
        asm volatile("red.release.gpu.global.add.u32 [%0], 1;"
                     :: "l"(&g_done[grp]) : "memory");
        if (slc == 0) {
            int c;
            do {
                asm volatile("ld.acquire.gpu.global.b32 %0, [%1];"
                             : "=r"(c) : "l"(&g_done[grp]) : "memory");
            } while (c < GJ);
            g_cnt[grp]  = 0;
            g_done[grp] = 0;
        }
    }
}

// ---------------- LayerNorm (in place) + prediction GEMM, 4 rows/block ----------------
#define RPB 4
__global__ void __launch_bounds__(128)
ln_pred_kernel(const float* __restrict__ gamma, const float* __restrict__ beta,
               const float* __restrict__ Wp,    const float* __restrict__ bp,
               float* __restrict__ hseq,        float* __restrict__ xhat)
{
    __shared__ float sh[RPB][H];    // 8 KB

    const int row0 = blockIdx.x * RPB;
    const int tid  = threadIdx.x;
    const int w    = tid >> 5;      // warp = row for LN, jo-group for GEMM
    const int l    = tid & 31;

    // ---- LN: warp w normalizes row row0+w ----
    float* hp = hseq + (size_t)(row0 + w) * H;
    float4 v[4];
    float s = 0.f, q = 0.f;
    #pragma unroll
    for (int i = 0; i < 4; i++) {
        v[i] = ((const float4*)hp)[l + 32 * i];
        s += v[i].x + v[i].y + v[i].z + v[i].w;
        q += v[i].x * v[i].x + v[i].y * v[i].y + v[i].z * v[i].z + v[i].w * v[i].w;
    }
    #pragma unroll
    for (int o = 16; o; o >>= 1) {
        s += __shfl_xor_sync(0xffffffffu, s, o);
        q += __shfl_xor_sync(0xffffffffu, q, o);
    }
    const float mu = s * (1.f / H);
    const float rs = rsqrtf(q * (1.f / H) - mu * mu + LN_EPS);

    #pragma unroll
    for (int i = 0; i < 4; i++) {
        float4 g4 = ((const float4*)gamma)[l + 32 * i];
        float4 b4 = ((const float4*)beta)[l + 32 * i];
        float4 o;
        o.x = (v[i].x - mu) * rs * g4.x + b4.x;
        o.y = (v[i].y - mu) * rs * g4.y + b4.y;
        o.z = (v[i].z - mu) * rs * g4.z + b4.z;
        o.w = (v[i].w - mu) * rs * g4.w + b4.w;
        ((float4*)hp)[l + 32 * i] = o;              // in-place normalized
        ((float4*)&sh[w][0])[l + 32 * i] = o;
    }
    __syncthreads();

    // ---- all 4 rows' k-chunk into registers (reused across 16 jo) ----
    float4 hreg[RPB][4];
    #pragma unroll
    for (int r = 0; r < RPB; r++)
        #pragma unroll
        for (int i = 0; i < 4; i++)
            hreg[r][i] = ((const float4*)&sh[r][0])[l + 32 * i];

    // ---- GEMM: warp w computes jo = 16w .. 16w+15 for all 4 rows ----
    #pragma unroll 4
    for (int jj = 0; jj < 16; jj++) {
        const int jo = w * 16 + jj;
        const float4* wp4 = (const float4*)(Wp + (size_t)jo * H);
        float acc[RPB] = {0.f, 0.f, 0.f, 0.f};
        #pragma unroll
        for (int i = 0; i < 4; i++) {
            float4 wv = wp4[l + 32 * i];
            #pragma unroll
            for (int r = 0; r < RPB; r++) {
                acc[r] += wv.x * hreg[r][i].x + wv.y * hreg[r][i].y
                        + wv.z * hreg[r][i].z + wv.w * hreg[r][i].w;
            }
        }
        #pragma unroll
        for (int o = 16; o; o >>= 1)
            #pragma unroll
            for (int r = 0; r < RPB; r++)
                acc[r] += __shfl_xor_sync(0xffffffffu, acc[r], o);
        if (l == 0) {
            const float bj = bp[jo];
            #pragma unroll
            for (int r = 0; r < RPB; r++)
                xhat[(size_t)(row0 + r) * D + jo] = acc[r] + bj;
        }
    }
}

extern "C" void kernel_launch(void* const* d_in, const int* in_sizes, int n_in,
                              void* d_out, int out_size)
{
    const float* x      = (const float*)d_in[0];
    const float* h0     = (const float*)d_in[1];
    const float* W_ih   = (const float*)d_in[2];
    const float* W_hh   = (const float*)d_in[3];
    const float* b_ih   = (const float*)d_in[4];
    const float* b_hh   = (const float*)d_in[5];
    const float* gamma  = (const float*)d_in[6];
    const float* beta   = (const float*)d_in[7];
    const float* W_pred = (const float*)d_in[8];
    const float* b_pred = (const float*)d_in[9];

    float* out      = (float*)d_out;
    float* out_hseq = out;                                   // (B, L, H)
    float* out_hN   = out + (size_t)B * L * H;               // (1, B, H)
    float* out_xhat = out_hN + (size_t)B * H;                // (B, L, D)

    cudaFuncSetAttribute(gru_kernel, cudaFuncAttributeMaxDynamicSharedMemorySize,
                         SMEM_BYTES);

    gru_kernel<<<GB * GJ, NT, SMEM_BYTES>>>(x, h0, W_ih, W_hh, b_ih, b_hh,
                                            out_hseq, out_hN);
    ln_pred_kernel<<<(B * L) / RPB, 128>>>(gamma, beta, W_pred, b_pred,
                                           out_hseq, out_xhat);
}

// round 10
// speedup vs baseline: 1.0982x; 1.0100x over previous
#include <cuda_runtime.h>

// Problem dims
#define B  64
#define L  1024
#define D  64
#define H  512
#define LN_EPS 1e-5f

// Partitioning: 8 batch-groups x 16 j-slices = 128 CTAs
#define GB 8     // batch groups
#define GJ 16    // hidden-column slices
#define BC 8     // batches per CTA   (B / GB)
#define JC 32    // j columns per CTA (H / GJ)
#define KG 16    // k-groups (warps; each owns 32 k-columns)
#define NT 512   // threads per CTA = JC * KG

// SMEM: Whh [3][128 k4][JC] float4  +  h_s [BC][H] float  +  red [4][BC][4][JC] float
#define WHH_F4     (3 * 128 * JC)                 // 12288 float4 = 196608 B
#define RED_F      (4 * BC * 4 * JC)              // 4096 floats  = 16384 B
#define SMEM_BYTES (WHH_F4 * 16 + BC * H * 4 + RED_F * 4)   // 229376 B

typedef unsigned long long ull;

// Global scratch (static — no allocations allowed)
__device__ float g_h[2][B * H];   // ping-pong hidden state
__device__ int   g_cnt[GB];       // per-group monotonic release counters (8/CTA/step)
__device__ int   g_done[GB];      // exit counters (for reset)

// ---------------- packed f32x2 helpers ----------------
__device__ __forceinline__ void ffma2(ull& acc, ull a, ull b) {
    asm("fma.rn.f32x2 %0, %1, %2, %0;" : "+l"(acc) : "l"(a), "l"(b));
}
__device__ __forceinline__ float upk_sum(ull v) {
    float lo, hi;
    asm("mov.b64 {%0, %1}, %2;" : "=f"(lo), "=f"(hi) : "l"(v));
    return lo + hi;
}

// ---------------- persistent recurrent kernel ----------------
__global__ void __launch_bounds__(NT, 1)
gru_kernel(const float* __restrict__ x,     // (B, L, D)
           const float* __restrict__ h0,    // (1, B, H)
           const float* __restrict__ W_ih,  // (3H, D)
           const float* __restrict__ W_hh,  // (3H, H)
           const float* __restrict__ b_ih,  // (3H)
           const float* __restrict__ b_hh,  // (3H)
           float* __restrict__ out_hseq,    // (B, L, H) — raw h, LN'd later in place
           float* __restrict__ out_hN)      // (1, B, H)
{
    extern __shared__ float4 smem[];
    float4* Whh_s = smem;                              // [3][128][JC] float4
    float*  h_s   = (float*)(smem + WHH_F4);           // [BC][H]
    float*  red   = h_s + BC * H;                      // [4 gates][BC][4 slots][JC]

    const int tid = threadIdx.x;
    const int j   = tid & 31;        // lane = hidden column within slice
    const int kg  = tid >> 5;        // warp id = k-group (0..15), 32 k each
    const int grp = blockIdx.x / GJ; // batch group
    const int slc = blockIdx.x % GJ; // j slice
    const int jg  = slc * JC + j;    // global hidden column
    const int bg0 = grp * BC;        // first global batch

    // ---- load W_hh slice into SMEM (once): 96 rows, 16 warps ----
    for (int rbase = 0; rbase < 96; rbase += 16) {
        int r  = rbase + kg;
        int g  = r >> 5;
        int jr = r & 31;
        const float4* src = (const float4*)(W_hh + ((size_t)(g * H + slc * JC + jr)) * H);
        #pragma unroll
        for (int c = 0; c < 4; c++) {
            int k4 = j + c * 32;
            Whh_s[(g * 128 + k4) * JC + jr] = src[k4];
        }
    }

    // ---- W_ih slice into registers: 4 floats of D per warp ----
    ull wih[3][2];
    #pragma unroll
    for (int g = 0; g < 3; g++) {
        const ull* src = (const ull*)(W_ih + (size_t)(g * H + jg) * D) + kg * 2;
        wih[g][0] = src[0];
        wih[g][1] = src[1];
    }

    // ---- biases for finalize (this thread's j column) ----
    const float bsr  = b_ih[jg]         + b_hh[jg];
    const float bsz  = b_ih[H + jg]     + b_hh[H + jg];
    const float bin_ = b_ih[2 * H + jg];
    const float bhn  = b_hh[2 * H + jg];

    // ---- stage initial h; h_old register for finalize threads ----
    {
        const float4* src = (const float4*)(h0 + (size_t)bg0 * H);
        float4* dst = (float4*)h_s;
        dst[tid]      = src[tid];
        dst[tid + NT] = src[tid + NT];
    }
    float h_old = (kg < 8) ? h0[(size_t)(bg0 + kg) * H + jg] : 0.f;

    // ---- accumulators; gi(t) computed directly into ar/az/an_ ----
    ull ar[BC], az[BC], an_[BC], ahn[BC];
    #define COMPUTE_GI(tt) do {                                                  \
        _Pragma("unroll")                                                        \
        for (int b = 0; b < BC; b++) {                                           \
            const ull* xp = (const ull*)(x + ((size_t)(bg0 + b) * L + (tt)) * D) \
                            + kg * 2;                                            \
            ull x0 = xp[0], x1 = xp[1];                                          \
            ar[b] = 0; az[b] = 0; an_[b] = 0;                                    \
            ffma2(ar[b],  wih[0][0], x0); ffma2(ar[b],  wih[0][1], x1);          \
            ffma2(az[b],  wih[1][0], x0); ffma2(az[b],  wih[1][1], x1);          \
            ffma2(an_[b], wih[2][0], x0); ffma2(an_[b], wih[2][1], x1);          \
        }                                                                        \
    } while (0)
    COMPUTE_GI(0);

    __syncthreads();

    for (int t = 0; t < L; t++) {
        // ---- recurrent GEMM over this warp's 32-col k-slab (acc pre-seeded with gi) ----
        #pragma unroll
        for (int b = 0; b < BC; b++) ahn[b] = 0;

        const int kb = kg * 8;
        #pragma unroll
        for (int k4m = 0; k4m < 8; k4m++) {
            const int k4 = kb + k4m;
            const ulonglong2 wr = *(const ulonglong2*)&Whh_s[(0 * 128 + k4) * JC + j];
            const ulonglong2 wz = *(const ulonglong2*)&Whh_s[(1 * 128 + k4) * JC + j];
            const ulonglong2 wn = *(const ulonglong2*)&Whh_s[(2 * 128 + k4) * JC + j];
            #pragma unroll
            for (int b = 0; b < BC; b++) {
                const ulonglong2 hv = *(const ulonglong2*)&h_s[b * H + k4 * 4];
                ffma2(ar[b],  wr.x, hv.x);  ffma2(ar[b],  wr.y, hv.y);
                ffma2(az[b],  wz.x, hv.x);  ffma2(az[b],  wz.y, hv.y);
                ffma2(ahn[b], wn.x, hv.x);  ffma2(ahn[b], wn.y, hv.y);
            }
        }

        // ---- 16-way cross-kg reduction: 4 phases into red[4][8][4][32] ----
        const int phs  = kg >> 2;
        const int slot = kg & 3;
        if (phs == 3) {
            #pragma unroll
            for (int b = 0; b < BC; b++) {
                red[((0 * BC + b) * 4 + slot) * JC + j] = upk_sum(ar[b]);
                red[((1 * BC + b) * 4 + slot) * JC + j] = upk_sum(az[b]);
                red[((2 * BC + b) * 4 + slot) * JC + j] = upk_sum(ahn[b]);
                red[((3 * BC + b) * 4 + slot) * JC + j] = upk_sum(an_[b]);
            }
        }
        __syncthreads();
        if (phs == 2) {
            #pragma unroll
            for (int b = 0; b < BC; b++) {
                red[((0 * BC + b) * 4 + slot) * JC + j] += upk_sum(ar[b]);
                red[((1 * BC + b) * 4 + slot) * JC + j] += upk_sum(az[b]);
                red[((2 * BC + b) * 4 + slot) * JC + j] += upk_sum(ahn[b]);
                red[((3 * BC + b) * 4 + slot) * JC + j] += upk_sum(an_[b]);
            }
        }
        __syncthreads();
        if (phs == 1) {
            #pragma unroll
            for (int b = 0; b < BC; b++) {
                red[((0 * BC + b) * 4 + slot) * JC + j] += upk_sum(ar[b]);
                red[((1 * BC + b) * 4 + slot) * JC + j] += upk_sum(az[b]);
                red[((2 * BC + b) * 4 + slot) * JC + j] += upk_sum(ahn[b]);
                red[((3 * BC + b) * 4 + slot) * JC + j] += upk_sum(an_[b]);
            }
        }
        __syncthreads();
        if (phs == 0) {
            #pragma unroll
            for (int b = 0; b < BC; b++) {
                red[((0 * BC + b) * 4 + slot) * JC + j] += upk_sum(ar[b]);
                red[((1 * BC + b) * 4 + slot) * JC + j] += upk_sum(az[b]);
                red[((2 * BC + b) * 4 + slot) * JC + j] += upk_sum(ahn[b]);
                red[((3 * BC + b) * 4 + slot) * JC + j] += upk_sum(an_[b]);
            }
        }
        __syncthreads();

        // ---- finalize: warps 0-7, one (b=kg, j=lane) pair per thread ----
        if (kg < 8) {
            const int b = kg;
            float sr = 0.f, sz = 0.f, shn = 0.f, sn = 0.f;
            #pragma unroll
            for (int c = 0; c < 4; c++) {
                sr  += red[((0 * BC + b) * 4 + c) * JC + j];
                sz  += red[((1 * BC + b) * 4 + c) * JC + j];
                shn += red[((2 * BC + b) * 4 + c) * JC + j];
                sn  += red[((3 * BC + b) * 4 + c) * JC + j];
            }
            float er = __expf(-(sr + bsr));
            float r  = __fdividef(1.f, 1.f + er);
            float ez = __expf(-(sz + bsz));
            float z  = __fdividef(1.f, 1.f + ez);
            float ta = sn + bin_ + r * (shn + bhn);
            ta = fminf(fmaxf(ta, -20.f), 20.f);
            float en = __expf(-2.f * ta);
            float n  = __fdividef(1.f - en, 1.f + en);   // tanh(ta)
            float hnew = fmaf(z, h_old - n, n);          // (1-z)n + z*h
            h_old = hnew;

            const int bglob = bg0 + b;
            g_h[t & 1][(size_t)bglob * H + jg] = hnew;
            out_hseq[((size_t)bglob * L + t) * H + jg] = hnew;
            if (t == L - 1) out_hN[(size_t)bglob * H + jg] = hnew;

            // per-warp release: this warp's g_h row is done
            __syncwarp();
            if (j == 0 && t + 1 < L) {
                asm volatile("red.release.gpu.global.add.u32 [%0], 1;"
                             :: "l"(&g_cnt[grp]) : "memory");
            }
        }

        if (t + 1 < L) {
            // input projection for t+1 — into the (now dead) accumulators
            COMPUTE_GI(t + 1);

            if (tid == 0) {
                const int target = 8 * GJ * (t + 1);     // 8 releases per CTA per step
                int c;
                do {
                    asm volatile("ld.acquire.gpu.global.b32 %0, [%1];"
                                 : "=r"(c) : "l"(&g_cnt[grp]) : "memory");
                } while (c < target);
            }
            __syncthreads();   // flag observed; red + h_s safe to overwrite

            // warp-local restage: only this warp's 32-column k-slab (1 KB)
            {
                const float* src = g_h[t & 1] + (size_t)bg0 * H + 32 * kg;
                float* dst = h_s + 32 * kg;
                #pragma unroll
                for (int i = 0; i < 2; i++) {
                    int idx = i * 32 + j;          // 0..63 float4s in slab
                    int b = idx >> 3, c4 = idx & 7;
                    float4 val = *(const float4*)(src + (size_t)b * H + c4 * 4);
                    *(float4*)(dst + b * H + c4 * 4) = val;
                }
                __syncwarp();
            }
        }
    }

    // ---- exit protocol: reset counters for next graph replay ----
    if (tid == 0) {
        asm volatile("red.release.gpu.global.add.u32 [%0], 1;"
                     :: "l"(&g_done[grp]) : "memory");
        if (slc == 0) {
            int c;
            do {
                asm volatile("ld.acquire.gpu.global.b32 %0, [%1];"
                             : "=r"(c) : "l"(&g_done[grp]) : "memory");
            } while (c < GJ);
            g_cnt[grp]  = 0;
            g_done[grp] = 0;
        }
    }
}

// ---------------- LayerNorm (in place) + prediction GEMM, 4 rows/block ----------------
#define RPB 4
__global__ void __launch_bounds__(128)
ln_pred_kernel(const float* __restrict__ gamma, const float* __restrict__ beta,
               const float* __restrict__ Wp,    const float* __restrict__ bp,
               float* __restrict__ hseq,        float* __restrict__ xhat)
{
    __shared__ float sh[RPB][H];    // 8 KB

    const int row0 = blockIdx.x * RPB;
    const int tid  = threadIdx.x;
    const int w    = tid >> 5;      // warp = row for LN, jo-group for GEMM
    const int l    = tid & 31;

    // ---- LN: warp w normalizes row row0+w ----
    float* hp = hseq + (size_t)(row0 + w) * H;
    float4 v[4];
    float s = 0.f, q = 0.f;
    #pragma unroll
    for (int i = 0; i < 4; i++) {
        v[i] = ((const float4*)hp)[l + 32 * i];
        s += v[i].x + v[i].y + v[i].z + v[i].w;
        q += v[i].x * v[i].x + v[i].y * v[i].y + v[i].z * v[i].z + v[i].w * v[i].w;
    }
    #pragma unroll
    for (int o = 16; o; o >>= 1) {
        s += __shfl_xor_sync(0xffffffffu, s, o);
        q += __shfl_xor_sync(0xffffffffu, q, o);
    }
    const float mu = s * (1.f / H);
    const float rs = rsqrtf(q * (1.f / H) - mu * mu + LN_EPS);

    #pragma unroll
    for (int i = 0; i < 4; i++) {
        float4 g4 = ((const float4*)gamma)[l + 32 * i];
        float4 b4 = ((const float4*)beta)[l + 32 * i];
        float4 o;
        o.x = (v[i].x - mu) * rs * g4.x + b4.x;
        o.y = (v[i].y - mu) * rs * g4.y + b4.y;
        o.z = (v[i].z - mu) * rs * g4.z + b4.z;
        o.w = (v[i].w - mu) * rs * g4.w + b4.w;
        ((float4*)hp)[l + 32 * i] = o;              // in-place normalized
        ((float4*)&sh[w][0])[l + 32 * i] = o;
    }
    __syncthreads();

    // ---- all 4 rows' k-chunk into registers (reused across 16 jo) ----
    float4 hreg[RPB][4];
    #pragma unroll
    for (int r = 0; r < RPB; r++)
        #pragma unroll
        for (int i = 0; i < 4; i++)
            hreg[r][i] = ((const float4*)&sh[r][0])[l + 32 * i];

    // ---- GEMM: warp w computes jo = 16w .. 16w+15 for all 4 rows ----
    #pragma unroll 4
    for (int jj = 0; jj < 16; jj++) {
        const int jo = w * 16 + jj;
        const float4* wp4 = (const float4*)(Wp + (size_t)jo * H);
        float acc[RPB] = {0.f, 0.f, 0.f, 0.f};
        #pragma unroll
        for (int i = 0; i < 4; i++) {
            float4 wv = wp4[l + 32 * i];
            #pragma unroll
            for (int r = 0; r < RPB; r++) {
                acc[r] += wv.x * hreg[r][i].x + wv.y * hreg[r][i].y
                        + wv.z * hreg[r][i].z + wv.w * hreg[r][i].w;
            }
        }
        #pragma unroll
        for (int o = 16; o; o >>= 1)
            #pragma unroll
            for (int r = 0; r < RPB; r++)
                acc[r] += __shfl_xor_sync(0xffffffffu, acc[r], o);
        if (l == 0) {
            const float bj = bp[jo];
            #pragma unroll
            for (int r = 0; r < RPB; r++)
                xhat[(size_t)(row0 + r) * D + jo] = acc[r] + bj;
        }
    }
}

extern "C" void kernel_launch(void* const* d_in, const int* in_sizes, int n_in,
                              void* d_out, int out_size)
{
    const float* x      = (const float*)d_in[0];
    const float* h0     = (const float*)d_in[1];
    const float* W_ih   = (const float*)d_in[2];
    const float* W_hh   = (const float*)d_in[3];
    const float* b_ih   = (const float*)d_in[4];
    const float* b_hh   = (const float*)d_in[5];
    const float* gamma  = (const float*)d_in[6];
    const float* beta   = (const float*)d_in[7];
    const float* W_pred = (const float*)d_in[8];
    const float* b_pred = (const float*)d_in[9];

    float* out      = (float*)d_out;
    float* out_hseq = out;                                   // (B, L, H)
    float* out_hN   = out + (size_t)B * L * H;               // (1, B, H)
    float* out_xhat = out_hN + (size_t)B * H;                // (B, L, D)

    cudaFuncSetAttribute(gru_kernel, cudaFuncAttributeMaxDynamicSharedMemorySize,
                         SMEM_BYTES);

    gru_kernel<<<GB * GJ, NT, SMEM_BYTES>>>(x, h0, W_ih, W_hh, b_ih, b_hh,
                                            out_hseq, out_hN);
    ln_pred_kernel<<<(B * L) / RPB, 128>>>(gamma, beta, W_pred, b_pred,
                                           out_hseq, out_xhat);
}